// round 2
// baseline (speedup 1.0000x reference)
#include <cuda_runtime.h>

// IFOPooling: h_t = f_t * h_{t-1} + i_t * z_t over S (contiguous), per (b,h) row.
// Persistent grid-stride kernel with register double-buffered row prefetch:
// next row's loads are issued before the current row's scan, keeping DRAM
// continuously fed across row boundaries.

constexpr int S_LEN = 2048;
constexpr int NTHR  = 256;
constexpr int PER   = S_LEN / NTHR;   // 8 elements per thread
constexpr int GRID  = 1216;           // 152 SMs * 8 slots

struct Row {
    float4 f0, f1, z0, z1, i0, i1;
};

__device__ __forceinline__ void load_row(Row& r,
                                         const float* __restrict__ f,
                                         const float* __restrict__ z,
                                         const float* __restrict__ i_,
                                         size_t base)
{
    r.f0 = *reinterpret_cast<const float4*>(f  + base);
    r.f1 = *reinterpret_cast<const float4*>(f  + base + 4);
    r.z0 = *reinterpret_cast<const float4*>(z  + base);
    r.z1 = *reinterpret_cast<const float4*>(z  + base + 4);
    r.i0 = *reinterpret_cast<const float4*>(i_ + base);
    r.i1 = *reinterpret_cast<const float4*>(i_ + base + 4);
}

__global__ __launch_bounds__(NTHR)
void ifo_scan_persist(const float* __restrict__ f,
                      const float* __restrict__ z,
                      const float* __restrict__ i_,
                      float* __restrict__ out,
                      int n_rows)
{
    const int t    = threadIdx.x;
    const int lane = t & 31;
    const int warp = t >> 5;
    const size_t toff = (size_t)t * PER;

    __shared__ float sA[NTHR / 32];
    __shared__ float sB[NTHR / 32];

    int row = blockIdx.x;
    if (row >= n_rows) return;

    Row cur;
    load_row(cur, f, z, i_, (size_t)row * S_LEN + toff);

    while (true) {
        const int next = row + GRID;
        const bool has_next = (next < n_rows);

        // ---- Prefetch next row BEFORE consuming current (overlap with scan) ----
        Row nxt;
        if (has_next)
            load_row(nxt, f, z, i_, (size_t)next * S_LEN + toff);

        // ---- Unpack current row ----
        float fv[PER] = {cur.f0.x, cur.f0.y, cur.f0.z, cur.f0.w,
                         cur.f1.x, cur.f1.y, cur.f1.z, cur.f1.w};
        float xv[PER] = {cur.i0.x * cur.z0.x, cur.i0.y * cur.z0.y,
                         cur.i0.z * cur.z0.z, cur.i0.w * cur.z0.w,
                         cur.i1.x * cur.z1.x, cur.i1.y * cur.z1.y,
                         cur.i1.z * cur.z1.z, cur.i1.w * cur.z1.w};

        // ---- Local chunk -> affine pair (A, B): h_out = A*h_in + B ----
        float A = 1.0f, Bc = 0.0f;
        #pragma unroll
        for (int j = 0; j < PER; j++) {
            Bc = fmaf(fv[j], Bc, xv[j]);
            A  = A * fv[j];
        }

        // ---- Intra-warp inclusive scan over pairs ----
        float Ai = A, Bi = Bc;
        #pragma unroll
        for (int d = 1; d < 32; d <<= 1) {
            float Au = __shfl_up_sync(0xffffffffu, Ai, d);
            float Bu = __shfl_up_sync(0xffffffffu, Bi, d);
            if (lane >= d) {
                Bi = fmaf(Ai, Bu, Bi);
                Ai = Ai * Au;
            }
        }

        // ---- Cross-warp prefix via shared memory ----
        __syncthreads();   // protect sA/sB reuse across loop iterations
        if (lane == 31) { sA[warp] = Ai; sB[warp] = Bi; }
        __syncthreads();

        float Aw = 1.0f, Bw = 0.0f;
        #pragma unroll
        for (int w = 0; w < NTHR / 32; w++) {
            if (w < warp) {
                Bw = fmaf(sA[w], Bw, sB[w]);
                Aw = Aw * sA[w];
            }
        }

        // ---- Thread's exclusive prefix within warp ----
        float Ae = __shfl_up_sync(0xffffffffu, Ai, 1);
        float Be = __shfl_up_sync(0xffffffffu, Bi, 1);
        if (lane == 0) { Ae = 1.0f; Be = 0.0f; }

        // Incoming h for this chunk (h0 = 0): h_in = Ae*Bw + Be
        float h = fmaf(Ae, Bw, Be);

        // ---- Replay chunk, store ----
        float ov[PER];
        #pragma unroll
        for (int j = 0; j < PER; j++) {
            h = fmaf(fv[j], h, xv[j]);
            ov[j] = h;
        }

        const size_t obase = (size_t)row * S_LEN + toff;
        *reinterpret_cast<float4*>(out + obase)     = make_float4(ov[0], ov[1], ov[2], ov[3]);
        *reinterpret_cast<float4*>(out + obase + 4) = make_float4(ov[4], ov[5], ov[6], ov[7]);

        if (!has_next) break;
        cur = nxt;
        row = next;
    }
}

extern "C" void kernel_launch(void* const* d_in, const int* in_sizes, int n_in,
                              void* d_out, int out_size)
{
    const float* f = (const float*)d_in[0];
    const float* z = (const float*)d_in[1];
    const float* i = (const float*)d_in[2];
    float* out = (float*)d_out;

    const int n_rows = in_sizes[0] / S_LEN;   // B*H = 16384
    const int grid = (n_rows < GRID) ? n_rows : GRID;
    ifo_scan_persist<<<grid, NTHR>>>(f, z, i, out, n_rows);
}